// round 15
// baseline (speedup 1.0000x reference)
#include <cuda_runtime.h>

// Scratch for per-row scores: s_i (includes +bias) and s_j.
__device__ float g_si[65536];
__device__ float g_sj[65536];

// ---------------------------------------------------------------------------
// Kernel 1 (primary): per-row dual dot product.
// 8 rows per warp, all 8 x-row loads front-batched. 256 blocks, single wave.
// ---------------------------------------------------------------------------
__global__ void __launch_bounds__(256)
row_scores_kernel(const float4* __restrict__ x4,
                  const float4* __restrict__ W4,
                  const float* __restrict__ bptr,
                  int n_rows)
{
    asm volatile("griddepcontrol.launch_dependents;" ::: "memory");

    const int lane = threadIdx.x & 31;
    const int gwarp = (blockIdx.x * blockDim.x + threadIdx.x) >> 5;
    const int rbase = gwarp * 8;
    if (rbase >= n_rows) return;

    float4 w1 = __ldg(W4 + lane);        // W[0:D]
    float4 w2 = __ldg(W4 + 32 + lane);   // W[D:2D]
    float bias = __ldg(bptr);

    float4 xv[8];
    #pragma unroll
    for (int k = 0; k < 8; k++) {
        int r = rbase + k;
        xv[k] = (r < n_rows) ? __ldg(x4 + (size_t)r * 32 + lane)
                             : make_float4(0.f, 0.f, 0.f, 0.f);
    }

    float s1[8], s2[8];
    #pragma unroll
    for (int k = 0; k < 8; k++) {
        s1[k] = xv[k].x * w1.x + xv[k].y * w1.y + xv[k].z * w1.z + xv[k].w * w1.w;
        s2[k] = xv[k].x * w2.x + xv[k].y * w2.y + xv[k].z * w2.z + xv[k].w * w2.w;
        #pragma unroll
        for (int off = 16; off > 0; off >>= 1) {
            s1[k] += __shfl_xor_sync(0xFFFFFFFFu, s1[k], off);
            s2[k] += __shfl_xor_sync(0xFFFFFFFFu, s2[k], off);
        }
    }

    if (lane == 0) {
        #pragma unroll
        for (int k = 0; k < 8; k++) {
            int r = rbase + k;
            if (r < n_rows) {
                g_si[r] = s1[k] + bias;
                g_sj[r] = s2[k];
            }
        }
    }
}

// ---------------------------------------------------------------------------
// Kernel 2 (secondary): fused elementwise pass.
//   out = 0.4*tanh((si+sj)/2) + 0.4 + 0.2*adj     [== 0.8*sigmoid + 0.2*adj]
// 4 float4 per thread, adj loads front-batched BEFORE griddepcontrol.wait.
// ---------------------------------------------------------------------------
#define VEC 4

__device__ __forceinline__ float sigterm(float z, float a)
{
    float t;
    asm("tanh.approx.f32 %0, %1;" : "=f"(t) : "f"(z * 0.5f));
    return fmaf(0.4f, t, fmaf(0.2f, a, 0.4f));
}

__device__ __forceinline__ float4 sigfuse(float si, float4 sj, float4 a)
{
    float4 r;
    r.x = sigterm(si + sj.x, a.x);
    r.y = sigterm(si + sj.y, a.y);
    r.z = sigterm(si + sj.z, a.z);
    r.w = sigterm(si + sj.w, a.w);
    return r;
}

__global__ void __launch_bounds__(256)
fuse_kernel(const float4* __restrict__ adj4,
            float4* __restrict__ out4,
            int total4, int log2_n4, int log2_n)
{
    const float4* __restrict__ sj4 = reinterpret_cast<const float4*>(g_sj);
    int base = blockIdx.x * (256 * VEC) + threadIdx.x;

    if (base + 3 * 256 < total4) {
        int e0 = base, e1 = base + 256, e2 = base + 512, e3 = base + 768;
        // Independent DRAM loads issued before the grid-dependency wait.
        float4 a0 = __ldcs(adj4 + e0);
        float4 a1 = __ldcs(adj4 + e1);
        float4 a2 = __ldcs(adj4 + e2);
        float4 a3 = __ldcs(adj4 + e3);

        asm volatile("griddepcontrol.wait;" ::: "memory");

        int mask = (1 << log2_n4) - 1;
        int r0 = e0 >> log2_n4, r1 = e1 >> log2_n4, r2 = e2 >> log2_n4, r3 = e3 >> log2_n4;
        float si0 = g_si[r0], si1 = g_si[r1], si2 = g_si[r2], si3 = g_si[r3];
        float4 s0 = sj4[((r0 >> log2_n) << log2_n4) + (e0 & mask)];
        float4 s1 = sj4[((r1 >> log2_n) << log2_n4) + (e1 & mask)];
        float4 s2 = sj4[((r2 >> log2_n) << log2_n4) + (e2 & mask)];
        float4 s3 = sj4[((r3 >> log2_n) << log2_n4) + (e3 & mask)];

        __stcs(out4 + e0, sigfuse(si0, s0, a0));
        __stcs(out4 + e1, sigfuse(si1, s1, a1));
        __stcs(out4 + e2, sigfuse(si2, s2, a2));
        __stcs(out4 + e3, sigfuse(si3, s3, a3));
    } else {
        asm volatile("griddepcontrol.wait;" ::: "memory");
        int mask = (1 << log2_n4) - 1;
        #pragma unroll
        for (int k = 0; k < VEC; k++) {
            int e = base + k * 256;
            if (e < total4) {
                float4 a = __ldcs(adj4 + e);
                int row = e >> log2_n4;
                float si = g_si[row];
                float4 sj = sj4[((row >> log2_n) << log2_n4) + (e & mask)];
                __stcs(out4 + e, sigfuse(si, sj, a));
            }
        }
    }
}

extern "C" void kernel_launch(void* const* d_in, const int* in_sizes, int n_in,
                              void* d_out, int out_size)
{
    const float* x   = (const float*)d_in[0];   // [B, N, D]
    const float* adj = (const float*)d_in[1];   // [B, N, N]
    const float* W   = (const float*)d_in[2];   // [2D]
    const float* b   = (const float*)d_in[3];   // scalar

    const int D = 128;
    int n_rows = in_sizes[0] / D;               // B*N = 16384
    long long N_ll = (long long)in_sizes[1] * D / in_sizes[0];
    int N = (int)N_ll;                           // 2048
    int log2_n = 0; while ((1 << log2_n) < N) log2_n++;
    int log2_n4 = log2_n - 2;

    // Kernel 1 (primary): 8 rows/warp -> n_rows/8 warps -> /8 blocks of 256.
    {
        int warps = (n_rows + 7) / 8;
        int blocks = (warps + 7) / 8;            // 256 blocks for 16384 rows
        row_scores_kernel<<<blocks, 256>>>(
            (const float4*)x, (const float4*)W, b, n_rows);
    }

    // Kernel 2 (secondary) with programmatic dependent launch.
    {
        int total4 = out_size / 4;               // 8.39M
        int per_block = 256 * VEC;
        int blocks = (total4 + per_block - 1) / per_block;

        cudaLaunchAttribute attrs[1];
        attrs[0].id = cudaLaunchAttributeProgrammaticStreamSerialization;
        attrs[0].val.programmaticStreamSerializationAllowed = 1;

        cudaLaunchConfig_t cfg = {};
        cfg.gridDim = dim3((unsigned)blocks, 1, 1);
        cfg.blockDim = dim3(256, 1, 1);
        cfg.dynamicSmemBytes = 0;
        cfg.stream = 0;
        cfg.attrs = attrs;
        cfg.numAttrs = 1;

        cudaError_t err = cudaLaunchKernelEx(&cfg, fuse_kernel,
            (const float4*)adj, (float4*)d_out, total4, log2_n4, log2_n);
        if (err != cudaSuccess) {
            cudaGetLastError();
            fuse_kernel<<<blocks, 256>>>(
                (const float4*)adj, (float4*)d_out, total4, log2_n4, log2_n);
        }
    }
}

// round 16
// speedup vs baseline: 1.0180x; 1.0180x over previous
#include <cuda_runtime.h>

// Scratch for per-row scores: s_i (includes +bias) and s_j.
__device__ float g_si[65536];
__device__ float g_sj[65536];

// ---------------------------------------------------------------------------
// Kernel 1 (primary): per-row dual dot product.
// 8 rows per warp, all 8 x-row loads front-batched. 256 blocks, single wave.
// ---------------------------------------------------------------------------
__global__ void __launch_bounds__(256)
row_scores_kernel(const float4* __restrict__ x4,
                  const float4* __restrict__ W4,
                  const float* __restrict__ bptr,
                  int n_rows)
{
    asm volatile("griddepcontrol.launch_dependents;" ::: "memory");

    const int lane = threadIdx.x & 31;
    const int gwarp = (blockIdx.x * blockDim.x + threadIdx.x) >> 5;
    const int rbase = gwarp * 8;
    if (rbase >= n_rows) return;

    float4 w1 = __ldg(W4 + lane);        // W[0:D]
    float4 w2 = __ldg(W4 + 32 + lane);   // W[D:2D]
    float bias = __ldg(bptr);

    float4 xv[8];
    #pragma unroll
    for (int k = 0; k < 8; k++) {
        int r = rbase + k;
        xv[k] = (r < n_rows) ? __ldg(x4 + (size_t)r * 32 + lane)
                             : make_float4(0.f, 0.f, 0.f, 0.f);
    }

    float s1[8], s2[8];
    #pragma unroll
    for (int k = 0; k < 8; k++) {
        s1[k] = xv[k].x * w1.x + xv[k].y * w1.y + xv[k].z * w1.z + xv[k].w * w1.w;
        s2[k] = xv[k].x * w2.x + xv[k].y * w2.y + xv[k].z * w2.z + xv[k].w * w2.w;
        #pragma unroll
        for (int off = 16; off > 0; off >>= 1) {
            s1[k] += __shfl_xor_sync(0xFFFFFFFFu, s1[k], off);
            s2[k] += __shfl_xor_sync(0xFFFFFFFFu, s2[k], off);
        }
    }

    if (lane == 0) {
        #pragma unroll
        for (int k = 0; k < 8; k++) {
            int r = rbase + k;
            if (r < n_rows) {
                g_si[r] = s1[k] + bias;
                g_sj[r] = s2[k];
            }
        }
    }
}

// ---------------------------------------------------------------------------
// Kernel 2 (secondary): fused elementwise pass.
//   out = 0.4*tanh((si+sj)/2) + 0.4 + 0.2*adj     [== 0.8*sigmoid + 0.2*adj]
// 512 threads/block, 4 float4 per thread (stride 512), adj loads
// front-batched BEFORE griddepcontrol.wait.
// ---------------------------------------------------------------------------
#define VEC 4
#define TPB 512

__device__ __forceinline__ float sigterm(float z, float a)
{
    float t;
    asm("tanh.approx.f32 %0, %1;" : "=f"(t) : "f"(z * 0.5f));
    return fmaf(0.4f, t, fmaf(0.2f, a, 0.4f));
}

__device__ __forceinline__ float4 sigfuse(float si, float4 sj, float4 a)
{
    float4 r;
    r.x = sigterm(si + sj.x, a.x);
    r.y = sigterm(si + sj.y, a.y);
    r.z = sigterm(si + sj.z, a.z);
    r.w = sigterm(si + sj.w, a.w);
    return r;
}

__global__ void __launch_bounds__(TPB)
fuse_kernel(const float4* __restrict__ adj4,
            float4* __restrict__ out4,
            int total4, int log2_n4, int log2_n)
{
    const float4* __restrict__ sj4 = reinterpret_cast<const float4*>(g_sj);
    int base = blockIdx.x * (TPB * VEC) + threadIdx.x;

    if (base + 3 * TPB < total4) {
        int e0 = base, e1 = base + TPB, e2 = base + 2 * TPB, e3 = base + 3 * TPB;
        // Independent DRAM loads issued before the grid-dependency wait.
        float4 a0 = __ldcs(adj4 + e0);
        float4 a1 = __ldcs(adj4 + e1);
        float4 a2 = __ldcs(adj4 + e2);
        float4 a3 = __ldcs(adj4 + e3);

        asm volatile("griddepcontrol.wait;" ::: "memory");

        int mask = (1 << log2_n4) - 1;
        int r0 = e0 >> log2_n4, r1 = e1 >> log2_n4, r2 = e2 >> log2_n4, r3 = e3 >> log2_n4;
        float si0 = g_si[r0], si1 = g_si[r1], si2 = g_si[r2], si3 = g_si[r3];
        float4 s0 = sj4[((r0 >> log2_n) << log2_n4) + (e0 & mask)];
        float4 s1 = sj4[((r1 >> log2_n) << log2_n4) + (e1 & mask)];
        float4 s2 = sj4[((r2 >> log2_n) << log2_n4) + (e2 & mask)];
        float4 s3 = sj4[((r3 >> log2_n) << log2_n4) + (e3 & mask)];

        __stcs(out4 + e0, sigfuse(si0, s0, a0));
        __stcs(out4 + e1, sigfuse(si1, s1, a1));
        __stcs(out4 + e2, sigfuse(si2, s2, a2));
        __stcs(out4 + e3, sigfuse(si3, s3, a3));
    } else {
        asm volatile("griddepcontrol.wait;" ::: "memory");
        int mask = (1 << log2_n4) - 1;
        #pragma unroll
        for (int k = 0; k < VEC; k++) {
            int e = base + k * TPB;
            if (e < total4) {
                float4 a = __ldcs(adj4 + e);
                int row = e >> log2_n4;
                float si = g_si[row];
                float4 sj = sj4[((row >> log2_n) << log2_n4) + (e & mask)];
                __stcs(out4 + e, sigfuse(si, sj, a));
            }
        }
    }
}

extern "C" void kernel_launch(void* const* d_in, const int* in_sizes, int n_in,
                              void* d_out, int out_size)
{
    const float* x   = (const float*)d_in[0];   // [B, N, D]
    const float* adj = (const float*)d_in[1];   // [B, N, N]
    const float* W   = (const float*)d_in[2];   // [2D]
    const float* b   = (const float*)d_in[3];   // scalar

    const int D = 128;
    int n_rows = in_sizes[0] / D;               // B*N = 16384
    long long N_ll = (long long)in_sizes[1] * D / in_sizes[0];
    int N = (int)N_ll;                           // 2048
    int log2_n = 0; while ((1 << log2_n) < N) log2_n++;
    int log2_n4 = log2_n - 2;

    // Kernel 1 (primary): 8 rows/warp -> n_rows/8 warps -> /8 blocks of 256.
    {
        int warps = (n_rows + 7) / 8;
        int blocks = (warps + 7) / 8;            // 256 blocks for 16384 rows
        row_scores_kernel<<<blocks, 256>>>(
            (const float4*)x, (const float4*)W, b, n_rows);
    }

    // Kernel 2 (secondary) with programmatic dependent launch.
    {
        int total4 = out_size / 4;               // 8.39M
        int per_block = TPB * VEC;
        int blocks = (total4 + per_block - 1) / per_block;  // 4096

        cudaLaunchAttribute attrs[1];
        attrs[0].id = cudaLaunchAttributeProgrammaticStreamSerialization;
        attrs[0].val.programmaticStreamSerializationAllowed = 1;

        cudaLaunchConfig_t cfg = {};
        cfg.gridDim = dim3((unsigned)blocks, 1, 1);
        cfg.blockDim = dim3(TPB, 1, 1);
        cfg.dynamicSmemBytes = 0;
        cfg.stream = 0;
        cfg.attrs = attrs;
        cfg.numAttrs = 1;

        cudaError_t err = cudaLaunchKernelEx(&cfg, fuse_kernel,
            (const float4*)adj, (float4*)d_out, total4, log2_n4, log2_n);
        if (err != cudaSuccess) {
            cudaGetLastError();
            fuse_kernel<<<blocks, TPB>>>(
                (const float4*)adj, (float4*)d_out, total4, log2_n4, log2_n);
        }
    }
}